// round 2
// baseline (speedup 1.0000x reference)
#include <cuda_runtime.h>
#include <cstdint>

// Problem shape (fixed by reference): B=32, C=256, H=64, W=64
// in:  d_in[0] = data_in   [B,C,H,W] f32  (33,554,432 elems)
//      d_in[1] = td_energy [C]       f32  (256)
//      d_in[2] = td_hist   [100,100] f32  (10,000)
// out: [ data_in copy | energy+meanabs | hist+1 ]  (f32)

static constexpr int B = 32;
static constexpr int C = 256;
static constexpr int HW = 64 * 64;          // 4096 floats per plane
static constexpr int PLANES = B * C;        // 8192
static constexpr long long N_DATA = (long long)PLANES * HW;  // 33,554,432
static constexpr float INV_N = 1.0f / (float)(B * HW);       // 1/131072
static constexpr int HIST_N = 10000;

// Persistent scratch for the cross-block channel reduction.
// Zero-initialized at module load; every kernel invocation restores it to
// zero (atomicExch on scratch, atomicInc-wrap on count), so each call does
// identical work on identical state -> deterministic & graph-replay-safe.
__device__ float        g_scratch[C];
__device__ unsigned int g_count[C];

// One block per (b,c) plane: copy 4096 floats (streaming float4) and
// accumulate sum(|x|). Partials funnel through g_scratch[c]; the 32nd
// (last) block for a channel finalizes out_energy[c]. Blocks 0..39 also
// handle the 10K-element hist (+1).
__global__ __launch_bounds__(256) void fused_all(
    const float4* __restrict__ in,
    float4* __restrict__ out,
    const float* __restrict__ td_energy,
    const float* __restrict__ td_hist,
    float* __restrict__ out_energy,
    float* __restrict__ out_hist) {

    const int plane = blockIdx.x;           // b*C + c
    const int c = plane & (C - 1);
    const size_t base = (size_t)plane * (HW / 4);   // float4 units

    // tiny side-task: hist (+1). 40 blocks x 256 threads covers 10000.
    if (plane < (HIST_N + 255) / 256) {
        int h = plane * 256 + threadIdx.x;
        if (h < HIST_N) out_hist[h] = td_hist[h] + 1.0f;
    }

    const float4* src = in + base;
    float4* dst = out + base;

    float s = 0.0f;
#pragma unroll
    for (int i = 0; i < 4; i++) {
        float4 v = __ldcs(src + threadIdx.x + i * 256);   // streaming load
        __stcs(dst + threadIdx.x + i * 256, v);           // streaming store
        s += fabsf(v.x) + fabsf(v.y) + fabsf(v.z) + fabsf(v.w);
    }

    // warp reduce
#pragma unroll
    for (int o = 16; o > 0; o >>= 1)
        s += __shfl_xor_sync(0xffffffffu, s, o);

    __shared__ float ws[8];
    if ((threadIdx.x & 31) == 0) ws[threadIdx.x >> 5] = s;
    __syncthreads();

    if (threadIdx.x == 0) {
        s = ws[0];
#pragma unroll
        for (int w = 1; w < 8; w++) s += ws[w];

        // publish partial, then last-arrival finalizes the channel
        atomicAdd(&g_scratch[c], s);
        __threadfence();
        unsigned old = atomicInc(&g_count[c], B - 1);  // wraps 31 -> 0
        if (old == B - 1) {
            // all 32 partials are visible (each add fenced before its inc)
            float tot = atomicExch(&g_scratch[c], 0.0f);  // read + reset
            out_energy[c] = td_energy[c] + tot * INV_N;
        }
    }
}

extern "C" void kernel_launch(void* const* d_in, const int* in_sizes, int n_in,
                              void* d_out, int out_size) {
    const float* data_in   = (const float*)d_in[0];
    const float* td_energy = (const float*)d_in[1];
    const float* td_hist   = (const float*)d_in[2];

    float* out        = (float*)d_out;
    float* out_energy = out + N_DATA;
    float* out_hist   = out_energy + C;

    fused_all<<<PLANES, 256>>>((const float4*)data_in, (float4*)out,
                               td_energy, td_hist, out_energy, out_hist);
}

// round 3
// speedup vs baseline: 1.0391x; 1.0391x over previous
#include <cuda_runtime.h>
#include <cstdint>

// Problem shape (fixed by reference): B=32, C=256, H=64, W=64
// in:  d_in[0] = data_in   [B,C,H,W] f32  (33,554,432 elems)
//      d_in[1] = td_energy [C]       f32  (256)
//      d_in[2] = td_hist   [100,100] f32  (10,000)
// out: [ data_in copy | energy+meanabs | hist+1 ]  (f32)

static constexpr int B = 32;
static constexpr int C = 256;
static constexpr int HW = 64 * 64;          // 4096 floats per plane
static constexpr int PLANES = B * C;        // 8192
static constexpr long long N_DATA = (long long)PLANES * HW;  // 33,554,432
static constexpr float INV_N = 1.0f / (float)(B * HW);       // 1/131072
static constexpr int HIST_N = 10000;

// Persistent scratch for the cross-block channel reduction.
// Zero-initialized at module load; every invocation restores it to zero
// (atomicExch on scratch, atomicInc-wrap on count) -> deterministic and
// graph-replay-safe.
__device__ float        g_scratch[C];
__device__ unsigned int g_count[C];

// One block per (b,c) plane: copy 4096 floats (plain float4 — streaming
// cache hints measurably HURT on sm_103a, R2 post-mortem) and accumulate
// sum(|x|). Partials funnel through g_scratch[c]; the 32nd (last) block
// per channel finalizes out_energy[c]. Blocks 0..39 also do hist (+1).
__global__ __launch_bounds__(256) void fused_all(
    const float4* __restrict__ in,
    float4* __restrict__ out,
    const float* __restrict__ td_energy,
    const float* __restrict__ td_hist,
    float* __restrict__ out_energy,
    float* __restrict__ out_hist) {

    const int plane = blockIdx.x;           // b*C + c
    const int c = plane & (C - 1);
    const size_t base = (size_t)plane * (HW / 4);   // float4 units

    // tiny side-task: hist (+1). 40 blocks x 256 threads covers 10000.
    if (plane < (HIST_N + 255) / 256) {
        int h = plane * 256 + threadIdx.x;
        if (h < HIST_N) out_hist[h] = td_hist[h] + 1.0f;
    }

    const float4* src = in + base;
    float4* dst = out + base;

    float s = 0.0f;
#pragma unroll
    for (int i = 0; i < 4; i++) {
        float4 v = src[threadIdx.x + i * 256];
        dst[threadIdx.x + i * 256] = v;
        s += fabsf(v.x) + fabsf(v.y) + fabsf(v.z) + fabsf(v.w);
    }

    // warp reduce
#pragma unroll
    for (int o = 16; o > 0; o >>= 1)
        s += __shfl_xor_sync(0xffffffffu, s, o);

    __shared__ float ws[8];
    if ((threadIdx.x & 31) == 0) ws[threadIdx.x >> 5] = s;
    __syncthreads();

    if (threadIdx.x == 0) {
        s = ws[0];
#pragma unroll
        for (int w = 1; w < 8; w++) s += ws[w];

        // publish partial; last arrival per channel finalizes
        atomicAdd(&g_scratch[c], s);
        __threadfence();
        unsigned old = atomicInc(&g_count[c], B - 1);  // wraps 31 -> 0
        if (old == B - 1) {
            float tot = atomicExch(&g_scratch[c], 0.0f);  // read + reset
            out_energy[c] = td_energy[c] + tot * INV_N;
        }
    }
}

extern "C" void kernel_launch(void* const* d_in, const int* in_sizes, int n_in,
                              void* d_out, int out_size) {
    const float* data_in   = (const float*)d_in[0];
    const float* td_energy = (const float*)d_in[1];
    const float* td_hist   = (const float*)d_in[2];

    float* out        = (float*)d_out;
    float* out_energy = out + N_DATA;
    float* out_hist   = out_energy + C;

    fused_all<<<PLANES, 256>>>((const float4*)data_in, (float4*)out,
                               td_energy, td_hist, out_energy, out_hist);
}

// round 4
// speedup vs baseline: 1.0442x; 1.0049x over previous
#include <cuda_runtime.h>
#include <cstdint>

// Problem shape (fixed by reference): B=32, C=256, H=64, W=64
// in:  d_in[0] = data_in   [B,C,H,W] f32  (33,554,432 elems)
//      d_in[1] = td_energy [C]       f32  (256)
//      d_in[2] = td_hist   [100,100] f32  (10,000)
// out: [ data_in copy | energy+meanabs | hist+1 ]  (f32)

static constexpr int B = 32;
static constexpr int C = 256;
static constexpr int HW = 64 * 64;          // 4096 floats per plane
static constexpr int PLANES = B * C;        // 8192
static constexpr long long N_DATA = (long long)PLANES * HW;  // 33,554,432
static constexpr float INV_N = 1.0f / (float)(B * HW);       // 1/131072
static constexpr int HIST_N = 10000;

// Persistent scratch (zero-init at load; every invocation restores zero ->
// deterministic & graph-replay-safe).
__device__ float        g_scratch[C];
__device__ unsigned int g_count[C];

// Fence-free arrival counter: release/acquire semantics carried by the L2
// atomic itself (no MEMBAR.GPU -> no CCTL.IVALL L1 flush; R3 post-mortem).
__device__ __forceinline__ unsigned inc_acq_rel(unsigned* p, unsigned wrap) {
    unsigned old;
    asm volatile("atom.acq_rel.gpu.inc.u32 %0, [%1], %2;"
                 : "=r"(old) : "l"(p), "r"(wrap) : "memory");
    return old;
}

// One block per (b,c) plane: copy 4096 floats (plain float4; streaming
// hints hurt on sm_103a — R2) and accumulate sum(|x|). Partials funnel
// through g_scratch[c]; the last-arriving block per channel finalizes
// out_energy[c]. Blocks 0..39 also do hist (+1).
__global__ __launch_bounds__(256) void fused_all(
    const float4* __restrict__ in,
    float4* __restrict__ out,
    const float* __restrict__ td_energy,
    const float* __restrict__ td_hist,
    float* __restrict__ out_energy,
    float* __restrict__ out_hist) {

    const int plane = blockIdx.x;           // b*C + c
    const int c = plane & (C - 1);
    const size_t base = (size_t)plane * (HW / 4);   // float4 units

    // tiny side-task: hist (+1). 40 blocks x 256 threads covers 10000.
    if (plane < (HIST_N + 255) / 256) {
        int h = plane * 256 + threadIdx.x;
        if (h < HIST_N) out_hist[h] = td_hist[h] + 1.0f;
    }

    const float4* src = in + base;
    float4* dst = out + base;

    float s = 0.0f;
#pragma unroll
    for (int i = 0; i < 4; i++) {
        float4 v = src[threadIdx.x + i * 256];
        dst[threadIdx.x + i * 256] = v;
        s += fabsf(v.x) + fabsf(v.y) + fabsf(v.z) + fabsf(v.w);
    }

    // warp reduce
#pragma unroll
    for (int o = 16; o > 0; o >>= 1)
        s += __shfl_xor_sync(0xffffffffu, s, o);

    __shared__ float ws[8];
    if ((threadIdx.x & 31) == 0) ws[threadIdx.x >> 5] = s;
    __syncthreads();

    if (threadIdx.x == 0) {
        s = ws[0];
#pragma unroll
        for (int w = 1; w < 8; w++) s += ws[w];

        // publish partial (relaxed red to L2)
        atomicAdd(&g_scratch[c], s);
        // arrival counter with acq_rel: orders the add above (release) and
        // makes all other blocks' adds visible to the last arrival (acquire)
        unsigned old = inc_acq_rel(&g_count[c], B - 1);  // wraps 31 -> 0
        if (old == B - 1) {
            float tot = atomicExch(&g_scratch[c], 0.0f);  // read + reset
            out_energy[c] = td_energy[c] + tot * INV_N;
        }
    }
}

extern "C" void kernel_launch(void* const* d_in, const int* in_sizes, int n_in,
                              void* d_out, int out_size) {
    const float* data_in   = (const float*)d_in[0];
    const float* td_energy = (const float*)d_in[1];
    const float* td_hist   = (const float*)d_in[2];

    float* out        = (float*)d_out;
    float* out_energy = out + N_DATA;
    float* out_hist   = out_energy + C;

    fused_all<<<PLANES, 256>>>((const float4*)data_in, (float4*)out,
                               td_energy, td_hist, out_energy, out_hist);
}